// round 10
// baseline (speedup 1.0000x reference)
#include <cuda_runtime.h>
#include <math.h>

#define NN 169343
#define EMAX 2400000
#define DIN 128
#define DH 256
#define DOUT 40

// ---------------- scratch (static device globals; alloc-free) ----------------
__device__ int   g_is64;             // 1 if edge_index is int64, 0 if int32
__device__ int   g_src[EMAX];
__device__ int   g_dst[EMAX];
__device__ float g_deg[NN];
__device__ float g_dinv[NN];
__device__ float g_enorm[EMAX];
__device__ float g_h[(size_t)NN * DH];    // h = x @ W (per layer, reused)
__device__ float g_agg[(size_t)NN * DH];  // aggregation buffer (reused)
__device__ float g_x2[(size_t)NN * DH];   // layer-1 output / layer-2 input

// ---------------- edge dtype probe ----------------
// If edge_index is int64 (values < 2^31 here), every odd 32-bit word is 0.
// If int32, odd words are random node indices; P(64 consecutive zeros) ~ 0.
__global__ void detect_dtype_k(const unsigned* __restrict__ ei_raw) {
    if (threadIdx.x == 0 && blockIdx.x == 0) {
        int is64 = 1;
        for (int i = 0; i < 64; i++)
            if (ei_raw[2 * i + 1] != 0u) { is64 = 0; break; }
        g_is64 = is64;
    }
}

// one-pass conversion to int32 src/dst arrays
__global__ void convert_edges_k(const void* __restrict__ ei, int E) {
    int e = blockIdx.x * blockDim.x + threadIdx.x;
    if (e >= E) return;
    if (g_is64) {
        const long long* p = (const long long*)ei;
        g_src[e] = (int)p[e];
        g_dst[e] = (int)p[(size_t)E + e];
    } else {
        const int* p = (const int*)ei;
        g_src[e] = p[e];
        g_dst[e] = p[E + e];
    }
}

// ---------------- degree / norm ----------------
__global__ void deg_init_k() {
    int i = blockIdx.x * blockDim.x + threadIdx.x;
    if (i < NN) g_deg[i] = 1.0f;
}

__global__ void deg_acc_k(int E) {
    int e = blockIdx.x * blockDim.x + threadIdx.x;
    if (e < E) atomicAdd(&g_deg[g_dst[e]], 1.0f);
}

__global__ void dinv_k() {
    int i = blockIdx.x * blockDim.x + threadIdx.x;
    if (i < NN) g_dinv[i] = rsqrtf(g_deg[i]);
}

__global__ void enorm_k(int E) {
    int e = blockIdx.x * blockDim.x + threadIdx.x;
    if (e < E) g_enorm[e] = g_dinv[g_src[e]] * g_dinv[g_dst[e]];
}

// ---------------- SGEMM: g_h[M,Nc] = A[M,K] @ B[K,Nc], row-major ----------------
#define BM 64
#define BN 64
#define BKK 16
#define TM 4
#define TN 4
// 256 threads: (BM/TM)*(BN/TN) = 16*16

__device__ __forceinline__ void sgemm_body(const float* __restrict__ A,
                                           const float* __restrict__ B,
                                           int M, int K, int Nc) {
    __shared__ float As[BKK][BM];
    __shared__ float Bs[BKK][BN];
    int tid = threadIdx.x;
    int block_row = blockIdx.y * BM;
    int block_col = blockIdx.x * BN;
    int tr = tid / (BN / TN);  // 0..15
    int tc = tid % (BN / TN);  // 0..15
    float acc[TM][TN] = {};

    for (int k0 = 0; k0 < K; k0 += BKK) {
        for (int i = tid; i < BM * BKK; i += 256) {
            int r = i / BKK, c = i % BKK;
            int gr = block_row + r;
            As[c][r] = (gr < M) ? A[(size_t)gr * K + k0 + c] : 0.0f;
        }
        for (int i = tid; i < BKK * BN; i += 256) {
            int r = i / BN, c = i % BN;
            int gc = block_col + c;
            Bs[r][c] = (gc < Nc) ? B[(size_t)(k0 + r) * Nc + gc] : 0.0f;
        }
        __syncthreads();
#pragma unroll
        for (int k = 0; k < BKK; k++) {
            float a[TM], b[TN];
#pragma unroll
            for (int i = 0; i < TM; i++) a[i] = As[k][tr * TM + i];
#pragma unroll
            for (int j = 0; j < TN; j++) b[j] = Bs[k][tc * TN + j];
#pragma unroll
            for (int i = 0; i < TM; i++)
#pragma unroll
                for (int j = 0; j < TN; j++) acc[i][j] += a[i] * b[j];
        }
        __syncthreads();
    }
#pragma unroll
    for (int i = 0; i < TM; i++) {
        int gr = block_row + tr * TM + i;
        if (gr >= M) continue;
#pragma unroll
        for (int j = 0; j < TN; j++) {
            int gc = block_col + tc * TN + j;
            if (gc < Nc) g_h[(size_t)gr * Nc + gc] = acc[i][j];
        }
    }
}

__global__ void sgemm_k(const float* __restrict__ A, const float* __restrict__ B,
                        int M, int K, int Nc) {
    sgemm_body(A, B, M, K, Nc);
}

// variant reading A from g_x2 (device-global scratch)
__global__ void sgemm_x2_k(const float* __restrict__ B, int M, int K, int Nc) {
    sgemm_body(g_x2, B, M, K, Nc);
}

// ---------------- seed: g_agg = g_h * self_norm + b ----------------
__global__ void seed_k(const float* __restrict__ b, int od) {
    size_t t = (size_t)blockIdx.x * blockDim.x + threadIdx.x;
    size_t total = (size_t)NN * od;
    if (t >= total) return;
    int i = (int)(t / od);
    int j = (int)(t % od);
    float dv = g_dinv[i];
    g_agg[t] = g_h[t] * (dv * dv) + b[j];
}

// ---------------- scatter: one warp per edge, float4 gather + scalar atomic add ----------------
__global__ void scatter_k(int E, int od) {
    int w = (blockIdx.x * blockDim.x + threadIdx.x) >> 5;
    int lane = threadIdx.x & 31;
    if (w >= E) return;
    int s = g_src[w];
    int d = g_dst[w];
    float nm = g_enorm[w];
    const float4* hs = (const float4*)(g_h + (size_t)s * od);
    float* ad = g_agg + (size_t)d * od;
    int n4 = od >> 2;
    for (int j = lane; j < n4; j += 32) {
        float4 v = __ldg(hs + j);
        atomicAdd(ad + 4 * j + 0, v.x * nm);
        atomicAdd(ad + 4 * j + 1, v.y * nm);
        atomicAdd(ad + 4 * j + 2, v.z * nm);
        atomicAdd(ad + 4 * j + 3, v.w * nm);
    }
}

// ---------------- BN + ReLU: reads g_agg; writes g_x2 (o==nullptr) or o ----------------
__global__ void bnrelu_k(float* __restrict__ o,
                         const float* __restrict__ g, const float* __restrict__ be,
                         const float* __restrict__ m, const float* __restrict__ v) {
    size_t t = (size_t)blockIdx.x * blockDim.x + threadIdx.x;
    if (t >= (size_t)NN * DH) return;
    int j = (int)(t % DH);
    float y = (g_agg[t] - m[j]) * rsqrtf(v[j] + 1e-5f) * g[j] + be[j];
    float r = fmaxf(y, 0.0f);
    if (o) o[t] = r; else g_x2[t] = r;
}

// ---------------- log-softmax over 40 classes, one warp per row (reads g_agg) ----------------
__global__ void logsoftmax_k(float* __restrict__ out) {
    int row = (blockIdx.x * blockDim.x + threadIdx.x) >> 5;
    int lane = threadIdx.x & 31;
    if (row >= NN) return;
    const float* r = g_agg + (size_t)row * DOUT;
    float v0 = r[lane];  // lane < 32 < 40: always valid
    float v1 = (lane + 32 < DOUT) ? r[lane + 32] : -INFINITY;
    float mx = fmaxf(v0, v1);
#pragma unroll
    for (int o = 16; o; o >>= 1) mx = fmaxf(mx, __shfl_xor_sync(0xFFFFFFFFu, mx, o));
    float s = expf(v0 - mx) + ((lane + 32 < DOUT) ? expf(v1 - mx) : 0.0f);
#pragma unroll
    for (int o = 16; o; o >>= 1) s += __shfl_xor_sync(0xFFFFFFFFu, s, o);
    float lse = mx + logf(s);
    out[(size_t)row * DOUT + lane] = v0 - lse;
    if (lane + 32 < DOUT) out[(size_t)row * DOUT + lane + 32] = v1 - lse;
}

// ---------------- launch ----------------
static inline int ceil_div(long long a, long long b) { return (int)((a + b - 1) / b); }

extern "C" void kernel_launch(void* const* d_in, const int* in_sizes, int n_in,
                              void* d_out, int out_size) {
    const float* x = (const float*)d_in[0];
    const void* ei = d_in[1];              // int32 or int64 — probed on device
    const float* W1 = (const float*)d_in[2];
    const float* b1 = (const float*)d_in[3];
    const float* g1 = (const float*)d_in[4];
    const float* be1 = (const float*)d_in[5];
    const float* m1 = (const float*)d_in[6];
    const float* v1 = (const float*)d_in[7];
    const float* W2 = (const float*)d_in[8];
    const float* b2 = (const float*)d_in[9];
    const float* g2 = (const float*)d_in[10];
    const float* be2 = (const float*)d_in[11];
    const float* m2 = (const float*)d_in[12];
    const float* v2 = (const float*)d_in[13];
    const float* W3 = (const float*)d_in[14];
    const float* b3 = (const float*)d_in[15];

    int E = in_sizes[1] / 2;

    float* out = (float*)d_out;
    float* emb = out + (size_t)NN * DOUT;  // node embeddings region

    const int T = 256;

    // --- edge dtype probe, conversion, normalization ---
    detect_dtype_k<<<1, 32>>>((const unsigned*)ei);
    convert_edges_k<<<ceil_div(E, T), T>>>(ei, E);
    deg_init_k<<<ceil_div(NN, T), T>>>();
    deg_acc_k<<<ceil_div(E, T), T>>>(E);
    dinv_k<<<ceil_div(NN, T), T>>>();
    enorm_k<<<ceil_div(E, T), T>>>(E);

    int scat_blocks = ceil_div((long long)E * 32, T);

    // --- layer 1: x[N,128] @ W1 -> g_h[N,256] ---
    {
        dim3 grid(ceil_div(DH, BN), ceil_div(NN, BM));
        sgemm_k<<<grid, 256>>>(x, W1, NN, DIN, DH);
        seed_k<<<ceil_div((long long)NN * DH, T), T>>>(b1, DH);
        scatter_k<<<scat_blocks, T>>>(E, DH);
        bnrelu_k<<<ceil_div((long long)NN * DH, T), T>>>(nullptr, g1, be1, m1, v1);
    }

    // --- layer 2: g_x2[N,256] @ W2 -> g_h ; BN output straight into d_out emb region ---
    {
        dim3 grid(ceil_div(DH, BN), ceil_div(NN, BM));
        sgemm_x2_k<<<grid, 256>>>(W2, NN, DH, DH);
        seed_k<<<ceil_div((long long)NN * DH, T), T>>>(b2, DH);
        scatter_k<<<scat_blocks, T>>>(E, DH);
        bnrelu_k<<<ceil_div((long long)NN * DH, T), T>>>(emb, g2, be2, m2, v2);
    }

    // --- layer 3: emb[N,256] @ W3 -> g_h[N,40] ; log_softmax -> d_out ---
    {
        dim3 grid(ceil_div(DOUT, BN), ceil_div(NN, BM));
        sgemm_k<<<grid, 256>>>(emb, W3, NN, DH, DOUT);
        seed_k<<<ceil_div((long long)NN * DOUT, T), T>>>(b3, DOUT);
        scatter_k<<<scat_blocks, T>>>(E, DOUT);
        logsoftmax_k<<<ceil_div((long long)NN * 32, T), T>>>(out);
    }
}

// round 13
// speedup vs baseline: 1.8895x; 1.8895x over previous
#include <cuda_runtime.h>
#include <math.h>

#define NN 169343
#define EMAX 2400000
#define DIN 128
#define DH 256
#define DOUT 40

// ---------------- scratch ----------------
__device__ int   g_is64;
__device__ int   g_src[EMAX];
__device__ int   g_dst[EMAX];
__device__ int   g_cnt[NN];
__device__ int   g_rowptr[NN + 1];
__device__ int   g_cursor[NN];
__device__ int   g_csr_src[EMAX];
__device__ float g_csr_w[EMAX];
__device__ int   g_bsum[1024];
__device__ float g_dinv[NN];
__device__ float g_h[(size_t)NN * DH];
__device__ float g_agg[(size_t)NN * DH];
__device__ float g_x2[(size_t)NN * DH];

// ---------------- edge dtype probe ----------------
__global__ void detect_dtype_k(const unsigned* __restrict__ ei_raw) {
    if (threadIdx.x == 0 && blockIdx.x == 0) {
        int is64 = 1;
        for (int i = 0; i < 64; i++)
            if (ei_raw[2 * i + 1] != 0u) { is64 = 0; break; }
        g_is64 = is64;
    }
}

__global__ void zero_cnt_k() {
    int i = blockIdx.x * blockDim.x + threadIdx.x;
    if (i < NN) g_cnt[i] = 0;
}

__global__ void convert_edges_k(const void* __restrict__ ei, int E) {
    int e = blockIdx.x * blockDim.x + threadIdx.x;
    if (e >= E) return;
    int s, d;
    if (g_is64) {
        const long long* p = (const long long*)ei;
        s = (int)p[e]; d = (int)p[(size_t)E + e];
    } else {
        const int* p = (const int*)ei;
        s = p[e]; d = p[E + e];
    }
    g_src[e] = s;
    g_dst[e] = d;
    atomicAdd(&g_cnt[d], 1);
}

__global__ void dinv_k() {
    int i = blockIdx.x * blockDim.x + threadIdx.x;
    if (i < NN) g_dinv[i] = rsqrtf((float)(g_cnt[i] + 1));
}

// ---------------- exclusive scan of g_cnt -> g_rowptr ----------------
__global__ void scan1_k() {
    __shared__ int s[256];
    int i = blockIdx.x * 256 + threadIdx.x;
    int v = (i < NN) ? g_cnt[i] : 0;
    s[threadIdx.x] = v;
    __syncthreads();
    for (int o = 1; o < 256; o <<= 1) {
        int t = (threadIdx.x >= o) ? s[threadIdx.x - o] : 0;
        __syncthreads();
        s[threadIdx.x] += t;
        __syncthreads();
    }
    if (i < NN) g_rowptr[i] = s[threadIdx.x] - v;
    if (threadIdx.x == 255) g_bsum[blockIdx.x] = s[255];
}

__global__ void scan2_k(int nb) {
    __shared__ int s[1024];
    int v = (threadIdx.x < nb) ? g_bsum[threadIdx.x] : 0;
    s[threadIdx.x] = v;
    __syncthreads();
    for (int o = 1; o < 1024; o <<= 1) {
        int t = (threadIdx.x >= o) ? s[threadIdx.x - o] : 0;
        __syncthreads();
        s[threadIdx.x] += t;
        __syncthreads();
    }
    if (threadIdx.x < nb) g_bsum[threadIdx.x] = s[threadIdx.x] - v;
}

__global__ void scan3_k(int E) {
    int i = blockIdx.x * blockDim.x + threadIdx.x;
    if (i < NN) {
        int r = g_rowptr[i] + g_bsum[i >> 8];
        g_rowptr[i] = r;
        g_cursor[i] = r;
    }
    if (i == NN) g_rowptr[NN] = E;
}

__global__ void fill_csr_k(int E) {
    int e = blockIdx.x * blockDim.x + threadIdx.x;
    if (e >= E) return;
    int s = g_src[e], d = g_dst[e];
    int pos = atomicAdd(&g_cursor[d], 1);
    g_csr_src[pos] = s;
    g_csr_w[pos] = g_dinv[s] * g_dinv[d];
}

// ---------------- SGEMM (unchanged, proven) ----------------
#define BM 64
#define BN 64
#define BKK 16
#define TM 4
#define TN 4

__device__ __forceinline__ void sgemm_body(const float* __restrict__ A,
                                           const float* __restrict__ B,
                                           int M, int K, int Nc) {
    __shared__ float As[BKK][BM];
    __shared__ float Bs[BKK][BN];
    int tid = threadIdx.x;
    int block_row = blockIdx.y * BM;
    int block_col = blockIdx.x * BN;
    int tr = tid / (BN / TN);
    int tc = tid % (BN / TN);
    float acc[TM][TN] = {};

    for (int k0 = 0; k0 < K; k0 += BKK) {
        for (int i = tid; i < BM * BKK; i += 256) {
            int r = i / BKK, c = i % BKK;
            int gr = block_row + r;
            As[c][r] = (gr < M) ? A[(size_t)gr * K + k0 + c] : 0.0f;
        }
        for (int i = tid; i < BKK * BN; i += 256) {
            int r = i / BN, c = i % BN;
            int gc = block_col + c;
            Bs[r][c] = (gc < Nc) ? B[(size_t)(k0 + r) * Nc + gc] : 0.0f;
        }
        __syncthreads();
#pragma unroll
        for (int k = 0; k < BKK; k++) {
            float a[TM], b[TN];
#pragma unroll
            for (int i = 0; i < TM; i++) a[i] = As[k][tr * TM + i];
#pragma unroll
            for (int j = 0; j < TN; j++) b[j] = Bs[k][tc * TN + j];
#pragma unroll
            for (int i = 0; i < TM; i++)
#pragma unroll
                for (int j = 0; j < TN; j++) acc[i][j] += a[i] * b[j];
        }
        __syncthreads();
    }
#pragma unroll
    for (int i = 0; i < TM; i++) {
        int gr = block_row + tr * TM + i;
        if (gr >= M) continue;
#pragma unroll
        for (int j = 0; j < TN; j++) {
            int gc = block_col + tc * TN + j;
            if (gc < Nc) g_h[(size_t)gr * Nc + gc] = acc[i][j];
        }
    }
}

__global__ void sgemm_k(const float* __restrict__ A, const float* __restrict__ B,
                        int M, int K, int Nc) {
    sgemm_body(A, B, M, K, Nc);
}

__global__ void sgemm_x2_k(const float* __restrict__ B, int M, int K, int Nc) {
    sgemm_body(g_x2, B, M, K, Nc);
}

// ---------------- seed: g_agg = g_h * self_norm + b (R10-proven) ----------------
__global__ void seed_k(const float* __restrict__ b, int od) {
    size_t t = (size_t)blockIdx.x * blockDim.x + threadIdx.x;
    size_t total = (size_t)NN * od;
    if (t >= total) return;
    int i = (int)(t / od);
    int j = (int)(t % od);
    float dv = g_dinv[i];
    g_agg[t] = g_h[t] * (dv * dv) + b[j];
}

// ---------------- CSR gather: warp per node, adds neighbor sum into g_agg ----------------
__global__ void csr_gather_k(int od) {
    int n = (blockIdx.x * blockDim.x + threadIdx.x) >> 5;
    int lane = threadIdx.x & 31;
    if (n >= NN) return;
    int beg = g_rowptr[n], end = g_rowptr[n + 1];
    if (od == DH) {
        float4 a0 = {0.f, 0.f, 0.f, 0.f}, a1 = {0.f, 0.f, 0.f, 0.f};
        for (int e = beg; e < end; e++) {
            int s = g_csr_src[e];
            float w = g_csr_w[e];
            const float4* hs = (const float4*)(g_h + (size_t)s * DH);
            float4 v0 = __ldg(hs + lane);
            float4 v1 = __ldg(hs + lane + 32);
            a0.x += v0.x * w; a0.y += v0.y * w; a0.z += v0.z * w; a0.w += v0.w * w;
            a1.x += v1.x * w; a1.y += v1.y * w; a1.z += v1.z * w; a1.w += v1.w * w;
        }
        float4* arow = (float4*)(g_agg + (size_t)n * DH);
        float4 c0 = arow[lane], c1 = arow[lane + 32];
        c0.x += a0.x; c0.y += a0.y; c0.z += a0.z; c0.w += a0.w;
        c1.x += a1.x; c1.y += a1.y; c1.z += a1.z; c1.w += a1.w;
        arow[lane] = c0;
        arow[lane + 32] = c1;
    } else {  // od == DOUT (40)
        bool hi = (lane < DOUT - 32);
        float a0 = 0.f, a1 = 0.f;
        for (int e = beg; e < end; e++) {
            int s = g_csr_src[e];
            float w = g_csr_w[e];
            const float* hs = g_h + (size_t)s * DOUT;
            a0 += hs[lane] * w;
            if (hi) a1 += hs[lane + 32] * w;
        }
        g_agg[(size_t)n * DOUT + lane] += a0;
        if (hi) g_agg[(size_t)n * DOUT + lane + 32] += a1;
    }
}

// ---------------- BN + ReLU (R10-proven) ----------------
__global__ void bnrelu_k(float* __restrict__ o,
                         const float* __restrict__ g, const float* __restrict__ be,
                         const float* __restrict__ m, const float* __restrict__ v) {
    size_t t = (size_t)blockIdx.x * blockDim.x + threadIdx.x;
    if (t >= (size_t)NN * DH) return;
    int j = (int)(t % DH);
    float y = (g_agg[t] - m[j]) * rsqrtf(v[j] + 1e-5f) * g[j] + be[j];
    float r = fmaxf(y, 0.0f);
    if (o) o[t] = r; else g_x2[t] = r;
}

// ---------------- log-softmax (R10-proven) ----------------
__global__ void logsoftmax_k(float* __restrict__ out) {
    int row = (blockIdx.x * blockDim.x + threadIdx.x) >> 5;
    int lane = threadIdx.x & 31;
    if (row >= NN) return;
    const float* r = g_agg + (size_t)row * DOUT;
    float v0 = r[lane];
    float v1 = (lane + 32 < DOUT) ? r[lane + 32] : -INFINITY;
    float mx = fmaxf(v0, v1);
#pragma unroll
    for (int o = 16; o; o >>= 1) mx = fmaxf(mx, __shfl_xor_sync(0xFFFFFFFFu, mx, o));
    float s = expf(v0 - mx) + ((lane + 32 < DOUT) ? expf(v1 - mx) : 0.0f);
#pragma unroll
    for (int o = 16; o; o >>= 1) s += __shfl_xor_sync(0xFFFFFFFFu, s, o);
    float lse = mx + logf(s);
    out[(size_t)row * DOUT + lane] = v0 - lse;
    if (lane + 32 < DOUT) out[(size_t)row * DOUT + lane + 32] = v1 - lse;
}

// ---------------- launch ----------------
static inline int ceil_div(long long a, long long b) { return (int)((a + b - 1) / b); }

extern "C" void kernel_launch(void* const* d_in, const int* in_sizes, int n_in,
                              void* d_out, int out_size) {
    const float* x = (const float*)d_in[0];
    const void* ei = d_in[1];
    const float* W1 = (const float*)d_in[2];
    const float* b1 = (const float*)d_in[3];
    const float* g1 = (const float*)d_in[4];
    const float* be1 = (const float*)d_in[5];
    const float* m1 = (const float*)d_in[6];
    const float* v1 = (const float*)d_in[7];
    const float* W2 = (const float*)d_in[8];
    const float* b2 = (const float*)d_in[9];
    const float* g2 = (const float*)d_in[10];
    const float* be2 = (const float*)d_in[11];
    const float* m2 = (const float*)d_in[12];
    const float* v2 = (const float*)d_in[13];
    const float* W3 = (const float*)d_in[14];
    const float* b3 = (const float*)d_in[15];

    int E = in_sizes[1] / 2;

    float* out = (float*)d_out;
    float* emb = out + (size_t)NN * DOUT;

    const int T = 256;
    int nb = ceil_div(NN, 256);

    // --- CSR build ---
    detect_dtype_k<<<1, 32>>>((const unsigned*)ei);
    zero_cnt_k<<<ceil_div(NN, T), T>>>();
    convert_edges_k<<<ceil_div(E, T), T>>>(ei, E);
    dinv_k<<<ceil_div(NN, T), T>>>();
    scan1_k<<<nb, 256>>>();
    scan2_k<<<1, 1024>>>(nb);
    scan3_k<<<ceil_div(NN + 1, T), T>>>(E);
    fill_csr_k<<<ceil_div(E, T), T>>>(E);

    int warp_blocks = ceil_div((long long)NN * 32, T);

    // --- layer 1 ---
    {
        dim3 grid(ceil_div(DH, BN), ceil_div(NN, BM));
        sgemm_k<<<grid, 256>>>(x, W1, NN, DIN, DH);
        seed_k<<<ceil_div((long long)NN * DH, T), T>>>(b1, DH);
        csr_gather_k<<<warp_blocks, T>>>(DH);
        bnrelu_k<<<ceil_div((long long)NN * DH, T), T>>>(nullptr, g1, be1, m1, v1);
    }
    // --- layer 2 ---
    {
        dim3 grid(ceil_div(DH, BN), ceil_div(NN, BM));
        sgemm_x2_k<<<grid, 256>>>(W2, NN, DH, DH);
        seed_k<<<ceil_div((long long)NN * DH, T), T>>>(b2, DH);
        csr_gather_k<<<warp_blocks, T>>>(DH);
        bnrelu_k<<<ceil_div((long long)NN * DH, T), T>>>(emb, g2, be2, m2, v2);
    }
    // --- layer 3 ---
    {
        dim3 grid(ceil_div(DOUT, BN), ceil_div(NN, BM));
        sgemm_k<<<grid, 256>>>(emb, W3, NN, DH, DOUT);
        seed_k<<<ceil_div((long long)NN * DOUT, T), T>>>(b3, DOUT);
        csr_gather_k<<<warp_blocks, T>>>(DOUT);
        logsoftmax_k<<<ceil_div((long long)NN * 32, T), T>>>(out);
    }
}

// round 16
// speedup vs baseline: 3.1737x; 1.6796x over previous
#include <cuda_runtime.h>
#include <math.h>

#define NN 169343
#define EMAX 2400000
#define DIN 128
#define DH 256
#define DOUT 40

// ---------------- scratch ----------------
__device__ int   g_is64;
__device__ int   g_src[EMAX];
__device__ int   g_dst[EMAX];
__device__ int   g_cnt[NN];
__device__ int   g_rowptr[NN + 1];
__device__ int   g_cursor[NN];
__device__ int   g_csr_src[EMAX];
__device__ float g_csr_w[EMAX];
__device__ int   g_bsum[1024];
__device__ float g_dinv[NN];
__device__ float g_h[(size_t)NN * DH];
__device__ float g_agg[(size_t)NN * DH];
__device__ float g_x2[(size_t)NN * DH];

// ---------------- edge dtype probe ----------------
__global__ void detect_dtype_k(const unsigned* __restrict__ ei_raw) {
    if (threadIdx.x == 0 && blockIdx.x == 0) {
        int is64 = 1;
        for (int i = 0; i < 64; i++)
            if (ei_raw[2 * i + 1] != 0u) { is64 = 0; break; }
        g_is64 = is64;
    }
}

__global__ void zero_cnt_k() {
    int i = blockIdx.x * blockDim.x + threadIdx.x;
    if (i < NN) g_cnt[i] = 0;
}

__global__ void convert_edges_k(const void* __restrict__ ei, int E) {
    int e = blockIdx.x * blockDim.x + threadIdx.x;
    if (e >= E) return;
    int s, d;
    if (g_is64) {
        const long long* p = (const long long*)ei;
        s = (int)p[e]; d = (int)p[(size_t)E + e];
    } else {
        const int* p = (const int*)ei;
        s = p[e]; d = p[E + e];
    }
    g_src[e] = s;
    g_dst[e] = d;
    atomicAdd(&g_cnt[d], 1);
}

__global__ void dinv_k() {
    int i = blockIdx.x * blockDim.x + threadIdx.x;
    if (i < NN) g_dinv[i] = rsqrtf((float)(g_cnt[i] + 1));
}

// ---------------- exclusive scan ----------------
__global__ void scan1_k() {
    __shared__ int s[256];
    int i = blockIdx.x * 256 + threadIdx.x;
    int v = (i < NN) ? g_cnt[i] : 0;
    s[threadIdx.x] = v;
    __syncthreads();
    for (int o = 1; o < 256; o <<= 1) {
        int t = (threadIdx.x >= o) ? s[threadIdx.x - o] : 0;
        __syncthreads();
        s[threadIdx.x] += t;
        __syncthreads();
    }
    if (i < NN) g_rowptr[i] = s[threadIdx.x] - v;
    if (threadIdx.x == 255) g_bsum[blockIdx.x] = s[255];
}

__global__ void scan2_k(int nb) {
    __shared__ int s[1024];
    int v = (threadIdx.x < nb) ? g_bsum[threadIdx.x] : 0;
    s[threadIdx.x] = v;
    __syncthreads();
    for (int o = 1; o < 1024; o <<= 1) {
        int t = (threadIdx.x >= o) ? s[threadIdx.x - o] : 0;
        __syncthreads();
        s[threadIdx.x] += t;
        __syncthreads();
    }
    if (threadIdx.x < nb) g_bsum[threadIdx.x] = s[threadIdx.x] - v;
}

__global__ void scan3_k(int E) {
    int i = blockIdx.x * blockDim.x + threadIdx.x;
    if (i < NN) {
        int r = g_rowptr[i] + g_bsum[i >> 8];
        g_rowptr[i] = r;
        g_cursor[i] = r;
    }
    if (i == NN) g_rowptr[NN] = E;
}

__global__ void fill_csr_k(int E) {
    int e = blockIdx.x * blockDim.x + threadIdx.x;
    if (e >= E) return;
    int s = g_src[e], d = g_dst[e];
    int pos = atomicAdd(&g_cursor[d], 1);
    g_csr_src[pos] = s;
    g_csr_w[pos] = g_dinv[s] * g_dinv[d];
}

// ---------------- tf32 tensor-core GEMM: g_h = A @ B ----------------
// block tile 128x64, 256 threads = 8 warps (4m x 2n), warp tile 32x32
// mma.sync.aligned.m16n8k8.row.col.f32.tf32.tf32.f32
#define TBM 128
#define TBN 64
#define TBK 16

__device__ __forceinline__ unsigned f2tf32(float f) {
    unsigned u;
    asm("cvt.rna.tf32.f32 %0, %1;" : "=r"(u) : "f"(f));
    return u;
}

__device__ __forceinline__ void mma_gemm_body(const float* __restrict__ A,
                                              const float* __restrict__ B,
                                              int M, int K, int Nc) {
    __shared__ unsigned As[TBM][TBK + 4];  // stride 20: frag LDS conflict-free
    __shared__ unsigned Bs[TBK][TBN + 8];  // stride 72: frag LDS conflict-free
    int tid = threadIdx.x;
    int lane = tid & 31;
    int wid = tid >> 5;
    int wm = wid >> 1;        // 0..3
    int wn = wid & 1;         // 0..1
    int gid = lane >> 2;      // 0..7
    int tid4 = lane & 3;      // 0..3
    int brow = blockIdx.y * TBM;
    int bcol = blockIdx.x * TBN;

    float c[2][4][4];
#pragma unroll
    for (int i = 0; i < 2; i++)
#pragma unroll
        for (int j = 0; j < 4; j++)
#pragma unroll
            for (int q = 0; q < 4; q++) c[i][j][q] = 0.0f;

    for (int k0 = 0; k0 < K; k0 += TBK) {
        // A tile: 128 rows x 16 cols; thread: rows (tid/4, tid/4+64), col4 = (tid%4)*4
        {
            int r = tid >> 2;
            int cc = (tid & 3) << 2;
#pragma unroll
            for (int h = 0; h < 2; h++) {
                int row = r + h * 64;
                int grow = brow + row;
                float4 v = {0.f, 0.f, 0.f, 0.f};
                if (grow < M) v = *(const float4*)(A + (size_t)grow * K + k0 + cc);
                As[row][cc + 0] = f2tf32(v.x);
                As[row][cc + 1] = f2tf32(v.y);
                As[row][cc + 2] = f2tf32(v.z);
                As[row][cc + 3] = f2tf32(v.w);
            }
        }
        // B tile: 16 rows x 64 cols; thread: row tid/16, col4 = (tid%16)*4
        {
            int r = tid >> 4;
            int cc = (tid & 15) << 2;
            int gcol = bcol + cc;
            float4 v = {0.f, 0.f, 0.f, 0.f};
            const float* src = B + (size_t)(k0 + r) * Nc + gcol;
            if (gcol + 3 < Nc) {
                v = *(const float4*)src;
            } else {
                if (gcol + 0 < Nc) v.x = src[0];
                if (gcol + 1 < Nc) v.y = src[1];
                if (gcol + 2 < Nc) v.z = src[2];
                if (gcol + 3 < Nc) v.w = src[3];
            }
            Bs[r][cc + 0] = f2tf32(v.x);
            Bs[r][cc + 1] = f2tf32(v.y);
            Bs[r][cc + 2] = f2tf32(v.z);
            Bs[r][cc + 3] = f2tf32(v.w);
        }
        __syncthreads();
#pragma unroll
        for (int kk = 0; kk < TBK; kk += 8) {
            unsigned a[2][4], b[4][2];
#pragma unroll
            for (int mf = 0; mf < 2; mf++) {
                int mb = wm * 32 + mf * 16;
                a[mf][0] = As[mb + gid][kk + tid4];
                a[mf][1] = As[mb + gid + 8][kk + tid4];
                a[mf][2] = As[mb + gid][kk + tid4 + 4];
                a[mf][3] = As[mb + gid + 8][kk + tid4 + 4];
            }
#pragma unroll
            for (int nf = 0; nf < 4; nf++) {
                int nb = wn * 32 + nf * 8;
                b[nf][0] = Bs[kk + tid4][nb + gid];
                b[nf][1] = Bs[kk + tid4 + 4][nb + gid];
            }
#pragma unroll
            for (int mf = 0; mf < 2; mf++)
#pragma unroll
                for (int nf = 0; nf < 4; nf++) {
                    asm volatile(
                        "mma.sync.aligned.m16n8k8.row.col.f32.tf32.tf32.f32 "
                        "{%0,%1,%2,%3}, {%4,%5,%6,%7}, {%8,%9}, {%0,%1,%2,%3};"
                        : "+f"(c[mf][nf][0]), "+f"(c[mf][nf][1]),
                          "+f"(c[mf][nf][2]), "+f"(c[mf][nf][3])
                        : "r"(a[mf][0]), "r"(a[mf][1]), "r"(a[mf][2]), "r"(a[mf][3]),
                          "r"(b[nf][0]), "r"(b[nf][1]));
                }
        }
        __syncthreads();
    }

    // store: d0 (row gid, col 2*tid4), d1 (+1 col), d2/d3 (row gid+8)
#pragma unroll
    for (int mf = 0; mf < 2; mf++)
#pragma unroll
        for (int nf = 0; nf < 4; nf++) {
            int row0 = brow + wm * 32 + mf * 16 + gid;
            int col0 = bcol + wn * 32 + nf * 8 + tid4 * 2;
            int row1 = row0 + 8;
            if (row0 < M) {
                if (col0 < Nc)     g_h[(size_t)row0 * Nc + col0]     = c[mf][nf][0];
                if (col0 + 1 < Nc) g_h[(size_t)row0 * Nc + col0 + 1] = c[mf][nf][1];
            }
            if (row1 < M) {
                if (col0 < Nc)     g_h[(size_t)row1 * Nc + col0]     = c[mf][nf][2];
                if (col0 + 1 < Nc) g_h[(size_t)row1 * Nc + col0 + 1] = c[mf][nf][3];
            }
        }
}

__global__ void mma_gemm_k(const float* __restrict__ A, const float* __restrict__ B,
                           int M, int K, int Nc) {
    mma_gemm_body(A, B, M, K, Nc);
}

__global__ void mma_gemm_x2_k(const float* __restrict__ B, int M, int K, int Nc) {
    mma_gemm_body(g_x2, B, M, K, Nc);
}

// ---------------- seed (R13-proven) ----------------
__global__ void seed_k(const float* __restrict__ b, int od) {
    size_t t = (size_t)blockIdx.x * blockDim.x + threadIdx.x;
    size_t total = (size_t)NN * od;
    if (t >= total) return;
    int i = (int)(t / od);
    int j = (int)(t % od);
    float dv = g_dinv[i];
    g_agg[t] = g_h[t] * (dv * dv) + b[j];
}

// ---------------- CSR gather (R13-proven) ----------------
__global__ void csr_gather_k(int od) {
    int n = (blockIdx.x * blockDim.x + threadIdx.x) >> 5;
    int lane = threadIdx.x & 31;
    if (n >= NN) return;
    int beg = g_rowptr[n], end = g_rowptr[n + 1];
    if (od == DH) {
        float4 a0 = {0.f, 0.f, 0.f, 0.f}, a1 = {0.f, 0.f, 0.f, 0.f};
        for (int e = beg; e < end; e++) {
            int s = g_csr_src[e];
            float w = g_csr_w[e];
            const float4* hs = (const float4*)(g_h + (size_t)s * DH);
            float4 v0 = __ldg(hs + lane);
            float4 v1 = __ldg(hs + lane + 32);
            a0.x += v0.x * w; a0.y += v0.y * w; a0.z += v0.z * w; a0.w += v0.w * w;
            a1.x += v1.x * w; a1.y += v1.y * w; a1.z += v1.z * w; a1.w += v1.w * w;
        }
        float4* arow = (float4*)(g_agg + (size_t)n * DH);
        float4 c0 = arow[lane], c1 = arow[lane + 32];
        c0.x += a0.x; c0.y += a0.y; c0.z += a0.z; c0.w += a0.w;
        c1.x += a1.x; c1.y += a1.y; c1.z += a1.z; c1.w += a1.w;
        arow[lane] = c0;
        arow[lane + 32] = c1;
    } else {
        bool hi = (lane < DOUT - 32);
        float a0 = 0.f, a1 = 0.f;
        for (int e = beg; e < end; e++) {
            int s = g_csr_src[e];
            float w = g_csr_w[e];
            const float* hs = g_h + (size_t)s * DOUT;
            a0 += hs[lane] * w;
            if (hi) a1 += hs[lane + 32] * w;
        }
        g_agg[(size_t)n * DOUT + lane] += a0;
        if (hi) g_agg[(size_t)n * DOUT + lane + 32] += a1;
    }
}

// ---------------- BN + ReLU (R13-proven) ----------------
__global__ void bnrelu_k(float* __restrict__ o,
                         const float* __restrict__ g, const float* __restrict__ be,
                         const float* __restrict__ m, const float* __restrict__ v) {
    size_t t = (size_t)blockIdx.x * blockDim.x + threadIdx.x;
    if (t >= (size_t)NN * DH) return;
    int j = (int)(t % DH);
    float y = (g_agg[t] - m[j]) * rsqrtf(v[j] + 1e-5f) * g[j] + be[j];
    float r = fmaxf(y, 0.0f);
    if (o) o[t] = r; else g_x2[t] = r;
}

// ---------------- log-softmax (R13-proven) ----------------
__global__ void logsoftmax_k(float* __restrict__ out) {
    int row = (blockIdx.x * blockDim.x + threadIdx.x) >> 5;
    int lane = threadIdx.x & 31;
    if (row >= NN) return;
    const float* r = g_agg + (size_t)row * DOUT;
    float v0 = r[lane];
    float v1 = (lane + 32 < DOUT) ? r[lane + 32] : -INFINITY;
    float mx = fmaxf(v0, v1);
#pragma unroll
    for (int o = 16; o; o >>= 1) mx = fmaxf(mx, __shfl_xor_sync(0xFFFFFFFFu, mx, o));
    float s = expf(v0 - mx) + ((lane + 32 < DOUT) ? expf(v1 - mx) : 0.0f);
#pragma unroll
    for (int o = 16; o; o >>= 1) s += __shfl_xor_sync(0xFFFFFFFFu, s, o);
    float lse = mx + logf(s);
    out[(size_t)row * DOUT + lane] = v0 - lse;
    if (lane + 32 < DOUT) out[(size_t)row * DOUT + lane + 32] = v1 - lse;
}

// ---------------- launch ----------------
static inline int ceil_div(long long a, long long b) { return (int)((a + b - 1) / b); }

extern "C" void kernel_launch(void* const* d_in, const int* in_sizes, int n_in,
                              void* d_out, int out_size) {
    const float* x = (const float*)d_in[0];
    const void* ei = d_in[1];
    const float* W1 = (const float*)d_in[2];
    const float* b1 = (const float*)d_in[3];
    const float* g1 = (const float*)d_in[4];
    const float* be1 = (const float*)d_in[5];
    const float* m1 = (const float*)d_in[6];
    const float* v1 = (const float*)d_in[7];
    const float* W2 = (const float*)d_in[8];
    const float* b2 = (const float*)d_in[9];
    const float* g2 = (const float*)d_in[10];
    const float* be2 = (const float*)d_in[11];
    const float* m2 = (const float*)d_in[12];
    const float* v2 = (const float*)d_in[13];
    const float* W3 = (const float*)d_in[14];
    const float* b3 = (const float*)d_in[15];

    int E = in_sizes[1] / 2;

    float* out = (float*)d_out;
    float* emb = out + (size_t)NN * DOUT;

    const int T = 256;
    int nb = ceil_div(NN, 256);

    // --- CSR build ---
    detect_dtype_k<<<1, 32>>>((const unsigned*)ei);
    zero_cnt_k<<<ceil_div(NN, T), T>>>();
    convert_edges_k<<<ceil_div(E, T), T>>>(ei, E);
    dinv_k<<<ceil_div(NN, T), T>>>();
    scan1_k<<<nb, 256>>>();
    scan2_k<<<1, 1024>>>(nb);
    scan3_k<<<ceil_div(NN + 1, T), T>>>(E);
    fill_csr_k<<<ceil_div(E, T), T>>>(E);

    int warp_blocks = ceil_div((long long)NN * 32, T);
    int mtiles = ceil_div(NN, TBM);

    // --- layer 1 ---
    {
        dim3 grid(ceil_div(DH, TBN), mtiles);
        mma_gemm_k<<<grid, 256>>>(x, W1, NN, DIN, DH);
        seed_k<<<ceil_div((long long)NN * DH, T), T>>>(b1, DH);
        csr_gather_k<<<warp_blocks, T>>>(DH);
        bnrelu_k<<<ceil_div((long long)NN * DH, T), T>>>(nullptr, g1, be1, m1, v1);
    }
    // --- layer 2 ---
    {
        dim3 grid(ceil_div(DH, TBN), mtiles);
        mma_gemm_x2_k<<<grid, 256>>>(W2, NN, DH, DH);
        seed_k<<<ceil_div((long long)NN * DH, T), T>>>(b2, DH);
        csr_gather_k<<<warp_blocks, T>>>(DH);
        bnrelu_k<<<ceil_div((long long)NN * DH, T), T>>>(emb, g2, be2, m2, v2);
    }
    // --- layer 3 ---
    {
        dim3 grid(ceil_div(DOUT, TBN), mtiles);
        mma_gemm_k<<<grid, 256>>>(emb, W3, NN, DH, DOUT);
        seed_k<<<ceil_div((long long)NN * DOUT, T), T>>>(b3, DOUT);
        csr_gather_k<<<warp_blocks, T>>>(DOUT);
        logsoftmax_k<<<ceil_div((long long)NN * 32, T), T>>>(out);
    }
}